// round 13
// baseline (speedup 1.0000x reference)
#include <cuda_runtime.h>
#include <cstdint>

#define S_GRID 7
#define N_CH 30
#define L_COORD 5.0f
#define L_NOOBJ 0.5f

#define TPB 128                     // threads per block = cells per tile
#define TILE_F (TPB * N_CH)         // 3840 floats per tensor per tile
#define TILE_BYTES (TILE_F * 4)     // 15360 B per tensor
#define STAGES 2
#define GRID_BLOCKS 392             // 3136 tiles / 392 = exactly 8 tiles per block
#define TILES_PER_BLOCK 8

__device__ float g_sums[4];         // [0]=xy+wh [1]=obj [2]=noobj [3]=class
__device__ unsigned int g_count;

__device__ __forceinline__ void mbar_init(uint32_t mbar, uint32_t count) {
    asm volatile("mbarrier.init.shared.b64 [%0], %1;" :: "r"(mbar), "r"(count) : "memory");
}
__device__ __forceinline__ void mbar_expect_tx(uint32_t mbar, uint32_t tx) {
    asm volatile("mbarrier.arrive.expect_tx.shared.b64 _, [%0], %1;"
                 :: "r"(mbar), "r"(tx) : "memory");
}
__device__ __forceinline__ void bulk_g2s(uint32_t dst, const void* src, uint32_t bytes,
                                         uint32_t mbar) {
    asm volatile("cp.async.bulk.shared::cta.global.mbarrier::complete_tx::bytes "
                 "[%0], [%1], %2, [%3];"
                 :: "r"(dst), "l"(src), "r"(bytes), "r"(mbar) : "memory");
}
__device__ __forceinline__ void bulk_prefetch_l2(const void* gptr, uint32_t bytes) {
    asm volatile("cp.async.bulk.prefetch.L2.global [%0], %1;"
                 :: "l"(gptr), "r"(bytes) : "memory");
}
__device__ __forceinline__ void mbar_wait(uint32_t mbar, uint32_t phase) {
    asm volatile(
        "{\n\t"
        ".reg .pred P;\n"
        "WAIT_%=:\n\t"
        "mbarrier.try_wait.parity.acquire.cta.shared::cta.b64 P, [%0], %1, 0x989680;\n\t"
        "@P bra DONE_%=;\n\t"
        "bra WAIT_%=;\n"
        "DONE_%=:\n\t"
        "}"
        :: "r"(mbar), "r"(phase) : "memory");
}

extern __shared__ float smem_dyn[];   // [STAGES][2 tensors][TILE_F]

__global__ __launch_bounds__(TPB) void yolo_loss_kernel(
    const float* __restrict__ pred,
    const float* __restrict__ tgt,
    float* __restrict__ out,
    float inv_bs, int ntiles, int nblocks)
{
    __shared__ __align__(8) unsigned long long mbar_store[STAGES];
    __shared__ float red[4][4];
    __shared__ int   s_is_last;

    const int tid = threadIdx.x;
    const int bid = blockIdx.x;
    const long tile_base = (long)bid * TILES_PER_BLOCK;   // contiguous range

    uint32_t mbar[STAGES], stage_addr[STAGES];
#pragma unroll
    for (int s = 0; s < STAGES; s++) {
        mbar[s] = (uint32_t)__cvta_generic_to_shared(&mbar_store[s]);
        stage_addr[s] = (uint32_t)__cvta_generic_to_shared(smem_dyn + s * 2 * TILE_F);
    }

    if (tid == 0) {
#pragma unroll
        for (int s = 0; s < STAGES; s++) mbar_init(mbar[s], 1);
        asm volatile("fence.proxy.async.shared::cta;" ::: "memory");
    }
    __syncthreads();

    float a_xywh = 0.0f, a_obj = 0.0f, a_noobj = 0.0f, a_cls = 0.0f;

    // ---- prologue: copy tile 0 into stage 0; prefetch tile 1 to L2 ----
    if (tid == 0) {
        mbar_expect_tx(mbar[0], 2 * TILE_BYTES);
        bulk_g2s(stage_addr[0],              pred + tile_base * TILE_F, TILE_BYTES, mbar[0]);
        bulk_g2s(stage_addr[0] + TILE_BYTES, tgt  + tile_base * TILE_F, TILE_BYTES, mbar[0]);
        bulk_prefetch_l2(pred + (tile_base + 1) * TILE_F, TILE_BYTES);
        bulk_prefetch_l2(tgt  + (tile_base + 1) * TILE_F, TILE_BYTES);
    }

    const float inv_s = 1.0f / 7.0f;   // mul-by-reciprocal; < 2 ulp vs fp32 div

#pragma unroll 1
    for (int it = 0; it < TILES_PER_BLOCK; it++) {
        if (tid == 0) {
            // issue TMA copy for tile it+1 into the other stage
            if (it + 1 < TILES_PER_BLOCK) {
                long t1 = tile_base + it + 1;
                int s1 = (it + 1) & 1;
                mbar_expect_tx(mbar[s1], 2 * TILE_BYTES);
                bulk_g2s(stage_addr[s1],              pred + t1 * TILE_F, TILE_BYTES, mbar[s1]);
                bulk_g2s(stage_addr[s1] + TILE_BYTES, tgt  + t1 * TILE_F, TILE_BYTES, mbar[s1]);
            }
            // prefetch tile it+2 into L2 (no smem cost, deepens DRAM queue)
            if (it + 2 < TILES_PER_BLOCK) {
                long t2 = tile_base + it + 2;
                bulk_prefetch_l2(pred + t2 * TILE_F, TILE_BYTES);
                bulk_prefetch_l2(tgt  + t2 * TILE_F, TILE_BYTES);
            }
        }

        int cur = it & 1;
        mbar_wait(mbar[cur], (uint32_t)((it >> 1) & 1));

        const float2* p2 = reinterpret_cast<const float2*>(
            smem_dyn + cur * 2 * TILE_F + tid * N_CH);
        const float2* t2 = reinterpret_cast<const float2*>(
            smem_dyn + cur * 2 * TILE_F + TILE_F + tid * N_CH);

        float2 pA = p2[0], pB = p2[1], pC = p2[2], pD = p2[3], pE = p2[4];
        float2 tA = t2[0], tB = t2[1], tC = t2[2];

        float conf_t = tC.x;                       // t[4]
        float coord = (conf_t > 0.0f) ? 1.0f : 0.0f;
        float noobj = (conf_t == 0.0f) ? 1.0f : 0.0f;

        float tax = tA.x * inv_s, tay = tA.y * inv_s;
        float thw = 0.5f * tB.x,  thh = 0.5f * tB.y;
        float tx1 = tax - thw, ty1 = tay - thh;
        float tx2 = tax + thw, ty2 = tay + thh;
        float area_t = (tx2 - tx1) * (ty2 - ty1);

        // box0 = p[0..4] : pA.x pA.y pB.x pB.y pC.x
        // box1 = p[5..9] : pC.y pD.x pD.y pE.x pE.y
        float bx[2] = { pA.x, pC.y };
        float by[2] = { pA.y, pD.x };
        float bw[2] = { pB.x, pD.y };
        float bh[2] = { pB.y, pE.x };
        float bc[2] = { pC.x, pE.y };

        float iou[2];
#pragma unroll
        for (int b = 0; b < 2; b++) {
            float pax = bx[b] * inv_s, pay = by[b] * inv_s;
            float phw = 0.5f * bw[b], phh = 0.5f * bh[b];
            float px1 = pax - phw, py1 = pay - phh;
            float px2 = pax + phw, py2 = pay + phh;

            float ltx = fmaxf(px1, tx1);
            float lty = fmaxf(py1, ty1);
            float rbx = fminf(px2, tx2);
            float rby = fminf(py2, ty2);
            float w = fmaxf(rbx - ltx, 0.0f);
            float h = fmaxf(rby - lty, 0.0f);
            float inter = w * h;
            float area_p = (px2 - px1) * (py2 - py1);
            iou[b] = inter / (area_p + area_t - inter);
        }

        // first-occurrence tie-break: pick box1 only if strictly greater
        bool take1 = (iou[1] > iou[0]);
        float max_iou = fmaxf(iou[0], iou[1]);
        float rx = take1 ? bx[1] : bx[0];
        float ry = take1 ? by[1] : by[0];
        float rw = take1 ? bw[1] : bw[0];
        float rh = take1 ? bh[1] : bh[0];
        float rc = take1 ? bc[1] : bc[0];

        float dx = rx - tA.x;
        float dy = ry - tA.y;
        float loss_xy = dx * dx + dy * dy;

        float dw = sqrtf(rw) - sqrtf(tB.x);
        float dh = sqrtf(rh) - sqrtf(tB.y);
        float loss_wh = dw * dw + dh * dh;

        float dob = rc - max_iou;
        float loss_obj = dob * dob;

        // class: floats 10..29 = float2 idx 5..14
        float loss_cls = 0.0f;
#pragma unroll
        for (int k = 5; k < 15; k++) {
            float2 pv = p2[k];
            float2 tv = t2[k];
            float d0 = pv.x - tv.x;
            float d1 = pv.y - tv.y;
            loss_cls += d0 * d0 + d1 * d1;
        }

        float d4 = pC.x - conf_t;            // p[4]-t[4]
        float d9 = pE.y - t2[4].y;           // p[9]-t[9]
        float loss_no = d4 * d4 + d9 * d9;

        a_xywh  += coord * (loss_xy + loss_wh);
        a_obj   += coord * loss_obj;
        a_noobj += noobj * loss_no;
        a_cls   += coord * loss_cls;

        __syncthreads();   // stage fully consumed before it is refilled
    }

    // ---- single block reduction ----
#pragma unroll
    for (int off = 16; off > 0; off >>= 1) {
        a_xywh  += __shfl_down_sync(0xFFFFFFFFu, a_xywh,  off);
        a_obj   += __shfl_down_sync(0xFFFFFFFFu, a_obj,   off);
        a_noobj += __shfl_down_sync(0xFFFFFFFFu, a_noobj, off);
        a_cls   += __shfl_down_sync(0xFFFFFFFFu, a_cls,   off);
    }

    int wid = tid >> 5;
    int lid = tid & 31;
    if (lid == 0) {
        red[0][wid] = a_xywh;
        red[1][wid] = a_obj;
        red[2][wid] = a_noobj;
        red[3][wid] = a_cls;
    }
    __syncthreads();

    if (tid == 0) {
        float v0 = red[0][0] + red[0][1] + red[0][2] + red[0][3];
        float v1 = red[1][0] + red[1][1] + red[1][2] + red[1][3];
        float v2 = red[2][0] + red[2][1] + red[2][2] + red[2][3];
        float v3 = red[3][0] + red[3][1] + red[3][2] + red[3][3];
        atomicAdd(&g_sums[0], v0);
        atomicAdd(&g_sums[1], v1);
        atomicAdd(&g_sums[2], v2);
        atomicAdd(&g_sums[3], v3);
        __threadfence();
        unsigned int old = atomicAdd(&g_count, 1u);
        s_is_last = (old == (unsigned int)(nblocks - 1)) ? 1 : 0;
    }
    __syncthreads();

    if (s_is_last && tid == 0) {
        __threadfence();
        volatile float* gs = g_sums;
        float xywh  = gs[0];
        float obj   = gs[1];
        float noobj = gs[2];
        float cls   = gs[3];
        out[0] = (L_COORD * xywh + obj + L_NOOBJ * noobj + cls) * inv_bs;
        out[1] = xywh;
        out[2] = obj;
        out[3] = noobj;
        out[4] = cls;
        g_sums[0] = 0.0f; g_sums[1] = 0.0f;
        g_sums[2] = 0.0f; g_sums[3] = 0.0f;
        g_count = 0u;
        __threadfence();
    }
}

extern "C" void kernel_launch(void* const* d_in, const int* in_sizes, int n_in,
                              void* d_out, int out_size) {
    const float* pred = (const float*)d_in[0];
    const float* tgt  = (const float*)d_in[1];
    int ncells = in_sizes[0] / N_CH;                 // 401408 = 3136 * 128
    int bs = ncells / (S_GRID * S_GRID);             // 8192
    int ntiles = ncells / TPB;                       // 3136 = 392 * 8
    int nblocks = GRID_BLOCKS;

    size_t smem_bytes = (size_t)STAGES * 2 * TILE_F * sizeof(float);  // 61440
    static int attr_set = 0;
    if (!attr_set) {
        cudaFuncSetAttribute(yolo_loss_kernel,
                             cudaFuncAttributeMaxDynamicSharedMemorySize,
                             (int)smem_bytes);
        attr_set = 1;
    }

    yolo_loss_kernel<<<nblocks, TPB, smem_bytes>>>(
        pred, tgt, (float*)d_out,
        1.0f / (float)bs, ntiles, nblocks);
}